// round 11
// baseline (speedup 1.0000x reference)
#include <cuda_runtime.h>
#include <math.h>

#define BATCH   64
#define T_LEN   262144
#define STEP    171
#define NSEG    1531
#define NPAIR   766
#define NPAD    768           // padded partials per batch (float4-friendly)

// ---------------- Compile-time tables (no init kernel) ----------------
struct Tables {
    float2 tw[512];   // W512^i = exp(-2*pi*i*I/512)
    float  wp[512];   // folded one-sided A-weight per full-spectrum bin
};

constexpr double PI_D = 3.141592653589793238462643383279502884;

constexpr double tsin_q(double x) {   // |x| <= pi/2
    double x2 = x * x, term = x, s = x;
    for (int n = 1; n <= 12; ++n) { term *= -x2 / (double)((2*n) * (2*n+1)); s += term; }
    return s;
}
constexpr double tcos_q(double x) {
    double x2 = x * x, term = 1.0, s = 1.0;
    for (int n = 1; n <= 12; ++n) { term *= -x2 / (double)((2*n-1) * (2*n)); s += term; }
    return s;
}
constexpr double tsqrt(double x) {
    double g = (x > 1.0) ? x : 1.0;
    for (int i = 0; i < 64; ++i) g = 0.5 * (g + x / g);
    return g;
}

constexpr Tables make_tables() {
    Tables tb{};
    for (int i = 0; i < 512; ++i) {
        int k = i & 127, q = (i >> 7) & 3;
        double th = PI_D * (double)k / 256.0;       // [0, pi/2)
        double c0 = tcos_q(th), s0 = tsin_q(th);
        double c = 0.0, s = 0.0;                    // cos/sin(pi*i/256)
        if      (q == 0) { c =  c0; s =  s0; }
        else if (q == 1) { c = -s0; s =  c0; }
        else if (q == 2) { c = -c0; s = -s0; }
        else             { c =  s0; s = -c0; }
        tb.tw[i].x = (float)c;
        tb.tw[i].y = (float)(-s);                   // exp(-i*theta)
        int kp = (i < 256) ? i : (512 - i);
        double w = 0.0;
        if (kp >= 1 && kp <= 243) {
            double f   = (double)kp * (3152.0 / 512.0);
            double fsq = f * f;
            double num = 12194.0 * 12194.0 * fsq * fsq;
            double den = (fsq + 20.6 * 20.6)
                       * tsqrt((fsq + 107.7 * 107.7) * (fsq + 737.9 * 737.9))
                       * (fsq + 12194.0 * 12194.0);
            double r = num / den;
            w = r * r * 1.5848931924611134852;      // 10^0.2
        }
        tb.wp[i] = (float)w;
    }
    return tb;
}

__device__ const Tables g_tab = make_tables();

// Scratch (static zero init; pad slots 766/767 per batch are never written)
__device__ __align__(16) float g_partial[BATCH * NPAD];

// In-place DFT-8 (natural order in/out): u_q = sum_p a_p * exp(-2pi i p q / 8)
__device__ __forceinline__ void dft8(float* xr, float* xi)
{
    const float C = 0.70710678118654752f;
    float e0r=xr[0]+xr[4], e0i=xi[0]+xi[4];
    float o0r=xr[0]-xr[4], o0i=xi[0]-xi[4];
    float e1r=xr[1]+xr[5], e1i=xi[1]+xi[5];
    float o1r=xr[1]-xr[5], o1i=xi[1]-xi[5];
    float e2r=xr[2]+xr[6], e2i=xi[2]+xi[6];
    float o2r=xr[2]-xr[6], o2i=xi[2]-xi[6];
    float e3r=xr[3]+xr[7], e3i=xi[3]+xi[7];
    float o3r=xr[3]-xr[7], o3i=xi[3]-xi[7];
    float t1r = C*(o1r + o1i), t1i = C*(o1i - o1r);
    float t2r = o2i,           t2i = -o2r;
    float t3r = C*(o3i - o3r), t3i = -C*(o3r + o3i);
    float a0r=e0r+e2r, a0i=e0i+e2i;
    float a1r=e0r-e2r, a1i=e0i-e2i;
    float a2r=e1r+e3r, a2i=e1i+e3i;
    float a3r=e1r-e3r, a3i=e1i-e3i;
    xr[0]=a0r+a2r; xi[0]=a0i+a2i;
    xr[4]=a0r-a2r; xi[4]=a0i-a2i;
    xr[2]=a1r+a3i; xi[2]=a1i-a3r;
    xr[6]=a1r-a3i; xi[6]=a1i+a3r;
    float b0r=o0r+t2r, b0i=o0i+t2i;
    float b1r=o0r-t2r, b1i=o0i-t2i;
    float b2r=t1r+t3r, b2i=t1i+t3i;
    float b3r=t1r-t3r, b3i=t1i-t3i;
    xr[1]=b0r+b2r; xi[1]=b0i+b2i;
    xr[5]=b0r-b2r; xi[5]=b0i-b2i;
    xr[3]=b1r+b3i; xi[3]=b1i-b3r;
    xr[7]=b1r-b3i; xi[7]=b1i+b3r;
}

__device__ __forceinline__ float2 cmul(float2 a, float2 b) {
    return make_float2(a.x * b.x - a.y * b.y, a.x * b.y + a.y * b.x);
}
__device__ __forceinline__ float2 cmulc(float2 a, float2 b) {  // a * conj(b)
    return make_float2(a.x * b.x + a.y * b.y, a.y * b.x - a.x * b.y);
}

// Apply twiddles W^{q*base}, q=1..7, from two exact bases w1=W^n, w4=W^{4n}.
__device__ __forceinline__ void twiddle7(float* vr, float* vi, float2 w1, float2 w4)
{
    float2 w[8];
    w[1] = w1;
    w[2] = cmul(w1, w1);
    w[3] = cmulc(w4, w1);
    w[4] = w4;
    w[5] = cmul(w4, w1);
    w[6] = cmul(w4, w[2]);
    w[7] = cmul(w4, w[3]);
    #pragma unroll
    for (int q = 1; q < 8; ++q) {
        float rr = vr[q], ii = vi[q];
        vr[q] = rr * w[q].x - ii * w[q].y;
        vi[q] = rr * w[q].y + ii * w[q].x;
    }
}

// One 128-thread block = 2 packed-pair FFT-512s (64 threads each, 8 pts/thread).
__global__ __launch_bounds__(128) void fft_pair_kernel(const float* __restrict__ x)
{
    // One shared exchange buffer, reused for both exchanges (both injective):
    //   Exchange 1: addr = 72*q  + t   (t < 64 < 72)
    //   Exchange 2: addr = 65*q2 + t   (t < 64 < 65)
    __shared__ float2 ex[2][576];
    __shared__ float  red[2][2];

    const int g = threadIdx.x >> 6;      // sub-FFT 0..1
    const int t = threadIdx.x & 63;      // 0..63 within FFT
    const int j = blockIdx.x * 2 + g;    // pair index 0..765
    const int b = blockIdx.y;

    const float* xa = x + (size_t)b * T_LEN + (size_t)j * (2 * STEP);
    const bool has_b = (2 * j + 1) < NSEG;   // false only for j == 765

    // Exact base twiddles for pass 1: W^t and W^{4t mod 512}.
    const float2 w1 = g_tab.tw[t];
    const float2 w4 = g_tab.tw[(4 * t) & 511];

    float vr[8], vi[8];

    // Window: win[t+64p] = 0.54 - 0.46*cos(th + p*pi/4) from exact base.
    {
        const float ct = w1.x, st = -w1.y;
        const float R2 = 0.70710678118654752f;
        const float WC[8] = {1.0f,  R2, 0.0f, -R2, -1.0f, -R2,  0.0f,  R2};
        const float WS[8] = {0.0f,  R2, 1.0f,  R2,  0.0f, -R2, -1.0f, -R2};
        #pragma unroll
        for (int p = 0; p < 8; ++p) {
            int i = t + (p << 6);
            float w = 0.54f - 0.46f * (ct * WC[p] - st * WS[p]);
            vr[p] = xa[i] * w;
            vi[p] = has_b ? xa[i + STEP] * w : 0.0f;
        }
    }

    // Pass 1: DFT-8 over p, twiddle W512^{t*q} (depth-2 products).
    dft8(vr, vi);
    twiddle7(vr, vi, w1, w4);

    // Exchange 1: store (q,t) -> 72q+t; load 72qp + m + 8s.
    #pragma unroll
    for (int q = 0; q < 8; ++q) ex[g][72 * q + t] = make_float2(vr[q], vi[q]);
    __syncthreads();
    const int qp = t >> 3, m = t & 7;
    #pragma unroll
    for (int s = 0; s < 8; ++s) {
        float2 v = ex[g][72 * qp + m + (s << 3)];
        vr[s] = v.x; vi[s] = v.y;
    }
    __syncthreads();   // buffer reuse (WAR guard)

    // Pass 2: DFT-8 over s, twiddle W64^{m*q2} (depth-2, bases W^{8m}, W^{32m}).
    dft8(vr, vi);
    twiddle7(vr, vi, g_tab.tw[m << 3], g_tab.tw[m << 5]);

    // Exchange 2: store t + 65*q2 (injective); load 8qp + r2 + 65m.
    #pragma unroll
    for (int q2 = 0; q2 < 8; ++q2) ex[g][t + 65 * q2] = make_float2(vr[q2], vi[q2]);
    __syncthreads();
    #pragma unroll
    for (int r2 = 0; r2 < 8; ++r2) {
        float2 v = ex[g][(qp << 3) + r2 + 65 * m];
        vr[r2] = v.x; vi[r2] = v.y;
    }

    // Pass 3: DFT-8 over r2. Thread owns bins k = 64*r2 + 8*m + qp.
    dft8(vr, vi);

    const int basek = (m << 3) + qp;
    float acc = 0.0f;
    #pragma unroll
    for (int r2 = 0; r2 < 8; ++r2) {
        int k = (r2 << 6) + basek;
        acc += g_tab.wp[k] * (vr[r2] * vr[r2] + vi[r2] * vi[r2]);
    }

    // Reduce 64 threads of this sub-group (deterministic tree)
    #pragma unroll
    for (int o = 16; o > 0; o >>= 1) acc += __shfl_down_sync(0xffffffffu, acc, o);
    if ((t & 31) == 0) red[g][t >> 5] = acc;
    __syncthreads();
    if (t == 0) g_partial[b * NPAD + j] = red[g][0] + red[g][1];
}

// Single block: 16 threads per batch -> band sum -> 10*log10 -> mean over 64.
__global__ __launch_bounds__(1024) void reduce_all_kernel(float cnorm, float* __restrict__ out)
{
    __shared__ float lv[64];
    __shared__ float red[2];
    const int tid = threadIdx.x;
    const int b = tid >> 4;
    const int l = tid & 15;

    // 768 floats per batch = 192 float4; 16 lanes x 12 vector loads.
    const float4* p4 = reinterpret_cast<const float4*>(g_partial + b * NPAD);
    float s = 0.0f;
    #pragma unroll
    for (int i = 0; i < 12; ++i) {
        float4 v = p4[l + (i << 4)];
        s += (v.x + v.y) + (v.z + v.w);
    }
    #pragma unroll
    for (int o = 8; o > 0; o >>= 1) s += __shfl_down_sync(0xffffffffu, s, o, 16);
    if (l == 0) lv[b] = 10.0f * log10f(s * cnorm);
    __syncthreads();

    if (tid < 64) {
        float v = lv[tid];
        #pragma unroll
        for (int o = 16; o > 0; o >>= 1) v += __shfl_down_sync(0xffffffffu, v, o);
        if ((tid & 31) == 0) red[tid >> 5] = v;
    }
    __syncthreads();
    if (tid == 0) out[0] = (red[0] + red[1]) * (1.0f / (float)BATCH);
}

extern "C" void kernel_launch(void* const* d_in, const int* in_sizes, int n_in,
                              void* d_out, int out_size)
{
    const float* x = (const float*)d_in[0];
    float* out = (float*)d_out;

    double wp = 0.0;
    for (int i = 0; i < 512; ++i) {
        double w = 0.54 - 0.46 * cos(2.0 * M_PI * (double)i / 512.0);
        float wf = (float)w;
        wp += (double)wf * (double)wf;
    }
    float cnorm = (float)(1.0 / (wp * 3152.0 * (double)NSEG));

    dim3 grid(NPAIR / 2, BATCH);
    fft_pair_kernel<<<grid, 128>>>(x);
    reduce_all_kernel<<<1, 1024>>>(cnorm, out);
}

// round 12
// speedup vs baseline: 1.1034x; 1.1034x over previous
#include <cuda_runtime.h>
#include <math.h>

#define BATCH   64
#define T_LEN   262144
#define STEP    171
#define NSEG    1531
#define NPAIR   766
#define NPAD    768           // padded partials per batch (float4-friendly)

// ---------------- Compile-time tables (no init kernel) ----------------
struct Tables {
    float2 tw[512];   // W512^i = exp(-2*pi*i*I/512)
    float  wp[512];   // folded one-sided A-weight per full-spectrum bin
};

constexpr double PI_D = 3.141592653589793238462643383279502884;

constexpr double tsin_q(double x) {   // |x| <= pi/2
    double x2 = x * x, term = x, s = x;
    for (int n = 1; n <= 12; ++n) { term *= -x2 / (double)((2*n) * (2*n+1)); s += term; }
    return s;
}
constexpr double tcos_q(double x) {
    double x2 = x * x, term = 1.0, s = 1.0;
    for (int n = 1; n <= 12; ++n) { term *= -x2 / (double)((2*n-1) * (2*n)); s += term; }
    return s;
}
constexpr double tsqrt(double x) {
    double g = (x > 1.0) ? x : 1.0;
    for (int i = 0; i < 64; ++i) g = 0.5 * (g + x / g);
    return g;
}

constexpr Tables make_tables() {
    Tables tb{};
    for (int i = 0; i < 512; ++i) {
        int k = i & 127, q = (i >> 7) & 3;
        double th = PI_D * (double)k / 256.0;       // [0, pi/2)
        double c0 = tcos_q(th), s0 = tsin_q(th);
        double c = 0.0, s = 0.0;                    // cos/sin(pi*i/256)
        if      (q == 0) { c =  c0; s =  s0; }
        else if (q == 1) { c = -s0; s =  c0; }
        else if (q == 2) { c = -c0; s = -s0; }
        else             { c =  s0; s = -c0; }
        tb.tw[i].x = (float)c;
        tb.tw[i].y = (float)(-s);                   // exp(-i*theta)
        int kp = (i < 256) ? i : (512 - i);
        double w = 0.0;
        if (kp >= 1 && kp <= 243) {
            double f   = (double)kp * (3152.0 / 512.0);
            double fsq = f * f;
            double num = 12194.0 * 12194.0 * fsq * fsq;
            double den = (fsq + 20.6 * 20.6)
                       * tsqrt((fsq + 107.7 * 107.7) * (fsq + 737.9 * 737.9))
                       * (fsq + 12194.0 * 12194.0);
            double r = num / den;
            w = r * r * 1.5848931924611134852;      // 10^0.2
        }
        tb.wp[i] = (float)w;
    }
    return tb;
}

__device__ const Tables g_tab = make_tables();

// Scratch (static zero init; pad slots 766/767 per batch are never written)
__device__ __align__(16) float g_partial[BATCH * NPAD];

// In-place DFT-8 (natural order in/out): u_q = sum_p a_p * exp(-2pi i p q / 8)
__device__ __forceinline__ void dft8(float* xr, float* xi)
{
    const float C = 0.70710678118654752f;
    float e0r=xr[0]+xr[4], e0i=xi[0]+xi[4];
    float o0r=xr[0]-xr[4], o0i=xi[0]-xi[4];
    float e1r=xr[1]+xr[5], e1i=xi[1]+xi[5];
    float o1r=xr[1]-xr[5], o1i=xi[1]-xi[5];
    float e2r=xr[2]+xr[6], e2i=xi[2]+xi[6];
    float o2r=xr[2]-xr[6], o2i=xi[2]-xi[6];
    float e3r=xr[3]+xr[7], e3i=xi[3]+xi[7];
    float o3r=xr[3]-xr[7], o3i=xi[3]-xi[7];
    float t1r = C*(o1r + o1i), t1i = C*(o1i - o1r);
    float t2r = o2i,           t2i = -o2r;
    float t3r = C*(o3i - o3r), t3i = -C*(o3r + o3i);
    float a0r=e0r+e2r, a0i=e0i+e2i;
    float a1r=e0r-e2r, a1i=e0i-e2i;
    float a2r=e1r+e3r, a2i=e1i+e3i;
    float a3r=e1r-e3r, a3i=e1i-e3i;
    xr[0]=a0r+a2r; xi[0]=a0i+a2i;
    xr[4]=a0r-a2r; xi[4]=a0i-a2i;
    xr[2]=a1r+a3i; xi[2]=a1i-a3r;
    xr[6]=a1r-a3i; xi[6]=a1i+a3r;
    float b0r=o0r+t2r, b0i=o0i+t2i;
    float b1r=o0r-t2r, b1i=o0i-t2i;
    float b2r=t1r+t3r, b2i=t1i+t3i;
    float b3r=t1r-t3r, b3i=t1i-t3i;
    xr[1]=b0r+b2r; xi[1]=b0i+b2i;
    xr[5]=b0r-b2r; xi[5]=b0i-b2i;
    xr[3]=b1r+b3i; xi[3]=b1i-b3r;
    xr[7]=b1r-b3i; xi[7]=b1i+b3r;
}

// One 128-thread block = 2 packed-pair FFT-512s (64 threads each, 8 pts/thread).
__global__ __launch_bounds__(128) void fft_pair_kernel(const float* __restrict__ x)
{
    // Separate exchange buffers (both maps injective) -> no WAR barrier:
    //   Exchange 1: addr = 72*q  + t   (t < 64 < 72), max 72*7+63 = 567
    //   Exchange 2: addr = 65*q2 + t   (t < 64 < 65), max 65*7+63 = 518
    __shared__ float2 ex1[2][568];
    __shared__ float2 ex2[2][520];
    __shared__ float  red[2][2];

    const int g = threadIdx.x >> 6;      // sub-FFT 0..1
    const int t = threadIdx.x & 63;      // 0..63 within FFT
    const int j = blockIdx.x * 2 + g;    // pair index 0..765
    const int b = blockIdx.y;

    const float* xa = x + (size_t)b * T_LEN + (size_t)j * (2 * STEP);
    const bool has_b = (2 * j + 1) < NSEG;   // false only for j == 765

    // Exact base twiddle: w1 = W512^t = (cos th, -sin th).
    const float2 w1 = g_tab.tw[t];

    float vr[8], vi[8];

    // Window: win[t+64p] = 0.54 - 0.46*cos(th + p*pi/4) from exact base.
    {
        const float ct = w1.x, st = -w1.y;
        const float R2 = 0.70710678118654752f;
        const float WC[8] = {1.0f,  R2, 0.0f, -R2, -1.0f, -R2,  0.0f,  R2};
        const float WS[8] = {0.0f,  R2, 1.0f,  R2,  0.0f, -R2, -1.0f, -R2};
        #pragma unroll
        for (int p = 0; p < 8; ++p) {
            int i = t + (p << 6);
            float w = 0.54f - 0.46f * (ct * WC[p] - st * WS[p]);
            vr[p] = xa[i] * w;
            vi[p] = has_b ? xa[i + STEP] * w : 0.0f;
        }
    }

    // Pass 1: DFT-8 over p, twiddle W512^{t*q} via exact-base rotation chain.
    dft8(vr, vi);
    {
        float cw = w1.x, sw = w1.y;
        #pragma unroll
        for (int q = 1; q < 8; ++q) {
            float rr = vr[q], ii = vi[q];
            vr[q] = rr * cw - ii * sw;
            vi[q] = rr * sw + ii * cw;
            float nc = cw * w1.x - sw * w1.y;
            sw = cw * w1.y + sw * w1.x;
            cw = nc;
        }
    }

    // Exchange 1: store (q,t) -> 72q+t; load 72qp + m + 8s.
    #pragma unroll
    for (int q = 0; q < 8; ++q) ex1[g][72 * q + t] = make_float2(vr[q], vi[q]);
    __syncthreads();
    const int qp = t >> 3, m = t & 7;
    #pragma unroll
    for (int s = 0; s < 8; ++s) {
        float2 v = ex1[g][72 * qp + m + (s << 3)];
        vr[s] = v.x; vi[s] = v.y;
    }

    // Pass 2: DFT-8 over s, twiddle W64^{m*q2} via exact-base chain.
    dft8(vr, vi);
    {
        const float2 w2 = g_tab.tw[m << 3];   // W512^{8m}
        float cw = w2.x, sw = w2.y;
        #pragma unroll
        for (int q2 = 1; q2 < 8; ++q2) {
            float rr = vr[q2], ii = vi[q2];
            vr[q2] = rr * cw - ii * sw;
            vi[q2] = rr * sw + ii * cw;
            float nc = cw * w2.x - sw * w2.y;
            sw = cw * w2.y + sw * w2.x;
            cw = nc;
        }
    }

    // Exchange 2: store t + 65*q2 (injective); load 8qp + r2 + 65m.
    #pragma unroll
    for (int q2 = 0; q2 < 8; ++q2) ex2[g][t + 65 * q2] = make_float2(vr[q2], vi[q2]);
    __syncthreads();
    #pragma unroll
    for (int r2 = 0; r2 < 8; ++r2) {
        float2 v = ex2[g][(qp << 3) + r2 + 65 * m];
        vr[r2] = v.x; vi[r2] = v.y;
    }

    // Pass 3: DFT-8 over r2. Thread owns bins k = 64*r2 + 8*m + qp.
    dft8(vr, vi);

    const int basek = (m << 3) + qp;
    float acc = 0.0f;
    #pragma unroll
    for (int r2 = 0; r2 < 8; ++r2) {
        int k = (r2 << 6) + basek;
        acc += g_tab.wp[k] * (vr[r2] * vr[r2] + vi[r2] * vi[r2]);
    }

    // Reduce 64 threads of this sub-group (deterministic tree)
    #pragma unroll
    for (int o = 16; o > 0; o >>= 1) acc += __shfl_down_sync(0xffffffffu, acc, o);
    if ((t & 31) == 0) red[g][t >> 5] = acc;
    __syncthreads();
    if (t == 0) g_partial[b * NPAD + j] = red[g][0] + red[g][1];
}

// Single block: 16 threads per batch -> band sum -> 10*log10 -> mean over 64.
__global__ __launch_bounds__(1024) void reduce_all_kernel(float cnorm, float* __restrict__ out)
{
    __shared__ float lv[64];
    __shared__ float red[2];
    const int tid = threadIdx.x;
    const int b = tid >> 4;
    const int l = tid & 15;

    // 768 floats per batch = 192 float4; 16 lanes x 12 vector loads.
    const float4* p4 = reinterpret_cast<const float4*>(g_partial + b * NPAD);
    float s = 0.0f;
    #pragma unroll
    for (int i = 0; i < 12; ++i) {
        float4 v = p4[l + (i << 4)];
        s += (v.x + v.y) + (v.z + v.w);
    }
    #pragma unroll
    for (int o = 8; o > 0; o >>= 1) s += __shfl_down_sync(0xffffffffu, s, o, 16);
    if (l == 0) lv[b] = 10.0f * log10f(s * cnorm);
    __syncthreads();

    if (tid < 64) {
        float v = lv[tid];
        #pragma unroll
        for (int o = 16; o > 0; o >>= 1) v += __shfl_down_sync(0xffffffffu, v, o);
        if ((tid & 31) == 0) red[tid >> 5] = v;
    }
    __syncthreads();
    if (tid == 0) out[0] = (red[0] + red[1]) * (1.0f / (float)BATCH);
}

extern "C" void kernel_launch(void* const* d_in, const int* in_sizes, int n_in,
                              void* d_out, int out_size)
{
    const float* x = (const float*)d_in[0];
    float* out = (float*)d_out;

    double wp = 0.0;
    for (int i = 0; i < 512; ++i) {
        double w = 0.54 - 0.46 * cos(2.0 * M_PI * (double)i / 512.0);
        float wf = (float)w;
        wp += (double)wf * (double)wf;
    }
    float cnorm = (float)(1.0 / (wp * 3152.0 * (double)NSEG));

    dim3 grid(NPAIR / 2, BATCH);
    fft_pair_kernel<<<grid, 128>>>(x);
    reduce_all_kernel<<<1, 1024>>>(cnorm, out);
}

// round 13
// speedup vs baseline: 1.1102x; 1.0062x over previous
#include <cuda_runtime.h>
#include <math.h>

#define BATCH   64
#define T_LEN   262144
#define STEP    171
#define NSEG    1531
#define NPAIR   766
#define NPAD    768           // padded partials per batch (float4-friendly)

// ---------------- Compile-time tables (no init kernel) ----------------
struct Tables {
    float2 tw[512];   // W512^i = exp(-2*pi*i*I/512)
    float  wp[512];   // folded one-sided A-weight per full-spectrum bin
};

constexpr double PI_D = 3.141592653589793238462643383279502884;

constexpr double tsin_q(double x) {   // |x| <= pi/2
    double x2 = x * x, term = x, s = x;
    for (int n = 1; n <= 12; ++n) { term *= -x2 / (double)((2*n) * (2*n+1)); s += term; }
    return s;
}
constexpr double tcos_q(double x) {
    double x2 = x * x, term = 1.0, s = 1.0;
    for (int n = 1; n <= 12; ++n) { term *= -x2 / (double)((2*n-1) * (2*n)); s += term; }
    return s;
}
constexpr double tsqrt(double x) {
    double g = (x > 1.0) ? x : 1.0;
    for (int i = 0; i < 64; ++i) g = 0.5 * (g + x / g);
    return g;
}

constexpr Tables make_tables() {
    Tables tb{};
    for (int i = 0; i < 512; ++i) {
        int k = i & 127, q = (i >> 7) & 3;
        double th = PI_D * (double)k / 256.0;       // [0, pi/2)
        double c0 = tcos_q(th), s0 = tsin_q(th);
        double c = 0.0, s = 0.0;                    // cos/sin(pi*i/256)
        if      (q == 0) { c =  c0; s =  s0; }
        else if (q == 1) { c = -s0; s =  c0; }
        else if (q == 2) { c = -c0; s = -s0; }
        else             { c =  s0; s = -c0; }
        tb.tw[i].x = (float)c;
        tb.tw[i].y = (float)(-s);                   // exp(-i*theta)
        int kp = (i < 256) ? i : (512 - i);
        double w = 0.0;
        if (kp >= 1 && kp <= 243) {
            double f   = (double)kp * (3152.0 / 512.0);
            double fsq = f * f;
            double num = 12194.0 * 12194.0 * fsq * fsq;
            double den = (fsq + 20.6 * 20.6)
                       * tsqrt((fsq + 107.7 * 107.7) * (fsq + 737.9 * 737.9))
                       * (fsq + 12194.0 * 12194.0);
            double r = num / den;
            w = r * r * 1.5848931924611134852;      // 10^0.2
        }
        tb.wp[i] = (float)w;
    }
    return tb;
}

__device__ const Tables g_tab = make_tables();

// Scratch (static zero init; pad slots 766/767 per batch are never written)
__device__ __align__(16) float g_partial[BATCH * NPAD];

// In-place DFT-8 (natural order in/out): u_q = sum_p a_p * exp(-2pi i p q / 8)
__device__ __forceinline__ void dft8(float* xr, float* xi)
{
    const float C = 0.70710678118654752f;
    float e0r=xr[0]+xr[4], e0i=xi[0]+xi[4];
    float o0r=xr[0]-xr[4], o0i=xi[0]-xi[4];
    float e1r=xr[1]+xr[5], e1i=xi[1]+xi[5];
    float o1r=xr[1]-xr[5], o1i=xi[1]-xi[5];
    float e2r=xr[2]+xr[6], e2i=xi[2]+xi[6];
    float o2r=xr[2]-xr[6], o2i=xi[2]-xi[6];
    float e3r=xr[3]+xr[7], e3i=xi[3]+xi[7];
    float o3r=xr[3]-xr[7], o3i=xi[3]-xi[7];
    float t1r = C*(o1r + o1i), t1i = C*(o1i - o1r);
    float t2r = o2i,           t2i = -o2r;
    float t3r = C*(o3i - o3r), t3i = -C*(o3r + o3i);
    float a0r=e0r+e2r, a0i=e0i+e2i;
    float a1r=e0r-e2r, a1i=e0i-e2i;
    float a2r=e1r+e3r, a2i=e1i+e3i;
    float a3r=e1r-e3r, a3i=e1i-e3i;
    xr[0]=a0r+a2r; xi[0]=a0i+a2i;
    xr[4]=a0r-a2r; xi[4]=a0i-a2i;
    xr[2]=a1r+a3i; xi[2]=a1i-a3r;
    xr[6]=a1r-a3i; xi[6]=a1i+a3r;
    float b0r=o0r+t2r, b0i=o0i+t2i;
    float b1r=o0r-t2r, b1i=o0i-t2i;
    float b2r=t1r+t3r, b2i=t1i+t3i;
    float b3r=t1r-t3r, b3i=t1i-t3i;
    xr[1]=b0r+b2r; xi[1]=b0i+b2i;
    xr[5]=b0r-b2r; xi[5]=b0i-b2i;
    xr[3]=b1r+b3i; xi[3]=b1i-b3r;
    xr[7]=b1r-b3i; xi[7]=b1i+b3r;
}

// One 128-thread block = 2 packed-pair FFT-512s (64 threads each, 8 pts/thread).
__global__ __launch_bounds__(128) void fft_pair_kernel(const float* __restrict__ x)
{
    // One shared exchange buffer, reused for both exchanges (both injective):
    //   Exchange 1: addr = 72*q  + t   (t < 64 < 72)
    //   Exchange 2: addr = 65*q2 + t   (t < 64 < 65)
    __shared__ float2 ex[2][576];
    __shared__ float  red[2][2];

    const int g = threadIdx.x >> 6;      // sub-FFT 0..1
    const int t = threadIdx.x & 63;      // 0..63 within FFT
    const int j = blockIdx.x * 2 + g;    // pair index 0..765
    const int b = blockIdx.y;

    const float* xa = x + (size_t)b * T_LEN + (size_t)j * (2 * STEP);
    const bool has_b = (2 * j + 1) < NSEG;   // false only for j == 765

    // Exact base twiddle: w1 = W512^t = (cos th, -sin th).
    const float2 w1 = g_tab.tw[t];

    float vr[8], vi[8];

    // Window: win[t+64p] = 0.54 - 0.46*cos(th + p*pi/4) from exact base.
    {
        const float ct = w1.x, st = -w1.y;
        const float R2 = 0.70710678118654752f;
        const float WC[8] = {1.0f,  R2, 0.0f, -R2, -1.0f, -R2,  0.0f,  R2};
        const float WS[8] = {0.0f,  R2, 1.0f,  R2,  0.0f, -R2, -1.0f, -R2};
        #pragma unroll
        for (int p = 0; p < 8; ++p) {
            int i = t + (p << 6);
            float w = 0.54f - 0.46f * (ct * WC[p] - st * WS[p]);
            vr[p] = xa[i] * w;
            vi[p] = has_b ? xa[i + STEP] * w : 0.0f;
        }
    }

    // Pass 1: DFT-8 over p, twiddle W512^{t*q} via exact-base rotation chain.
    dft8(vr, vi);
    {
        float cw = w1.x, sw = w1.y;
        #pragma unroll
        for (int q = 1; q < 8; ++q) {
            float rr = vr[q], ii = vi[q];
            vr[q] = rr * cw - ii * sw;
            vi[q] = rr * sw + ii * cw;
            float nc = cw * w1.x - sw * w1.y;
            sw = cw * w1.y + sw * w1.x;
            cw = nc;
        }
    }

    // Exchange 1: store (q,t) -> 72q+t; load 72qp + m + 8s.
    #pragma unroll
    for (int q = 0; q < 8; ++q) ex[g][72 * q + t] = make_float2(vr[q], vi[q]);
    __syncthreads();
    const int qp = t >> 3, m = t & 7;
    #pragma unroll
    for (int s = 0; s < 8; ++s) {
        float2 v = ex[g][72 * qp + m + (s << 3)];
        vr[s] = v.x; vi[s] = v.y;
    }
    __syncthreads();   // buffer reuse (WAR guard)

    // Pass 2: DFT-8 over s, twiddle W64^{m*q2} via exact-base chain.
    dft8(vr, vi);
    {
        const float2 w2 = g_tab.tw[m << 3];   // W512^{8m}
        float cw = w2.x, sw = w2.y;
        #pragma unroll
        for (int q2 = 1; q2 < 8; ++q2) {
            float rr = vr[q2], ii = vi[q2];
            vr[q2] = rr * cw - ii * sw;
            vi[q2] = rr * sw + ii * cw;
            float nc = cw * w2.x - sw * w2.y;
            sw = cw * w2.y + sw * w2.x;
            cw = nc;
        }
    }

    // Exchange 2: store t + 65*q2 (injective); load 8qp + r2 + 65m.
    #pragma unroll
    for (int q2 = 0; q2 < 8; ++q2) ex[g][t + 65 * q2] = make_float2(vr[q2], vi[q2]);
    __syncthreads();
    #pragma unroll
    for (int r2 = 0; r2 < 8; ++r2) {
        float2 v = ex[g][(qp << 3) + r2 + 65 * m];
        vr[r2] = v.x; vi[r2] = v.y;
    }

    // Pass 3: DFT-8 over r2. Thread owns bins k = 64*r2 + 8*m + qp.
    dft8(vr, vi);

    const int basek = (m << 3) + qp;
    float acc = 0.0f;
    #pragma unroll
    for (int r2 = 0; r2 < 8; ++r2) {
        int k = (r2 << 6) + basek;
        acc += g_tab.wp[k] * (vr[r2] * vr[r2] + vi[r2] * vi[r2]);
    }

    // Reduce 64 threads of this sub-group (deterministic tree)
    #pragma unroll
    for (int o = 16; o > 0; o >>= 1) acc += __shfl_down_sync(0xffffffffu, acc, o);
    if ((t & 31) == 0) red[g][t >> 5] = acc;
    __syncthreads();
    if (t == 0) g_partial[b * NPAD + j] = red[g][0] + red[g][1];
}

// Single block: 16 threads per batch -> band sum -> 10*log10 -> mean over 64.
__global__ __launch_bounds__(1024) void reduce_all_kernel(float cnorm, float* __restrict__ out)
{
    __shared__ float lv[64];
    __shared__ float red[2];
    const int tid = threadIdx.x;
    const int b = tid >> 4;
    const int l = tid & 15;

    // 768 floats per batch = 192 float4; 16 lanes x 12 vector loads.
    const float4* p4 = reinterpret_cast<const float4*>(g_partial + b * NPAD);
    float s = 0.0f;
    #pragma unroll
    for (int i = 0; i < 12; ++i) {
        float4 v = p4[l + (i << 4)];
        s += (v.x + v.y) + (v.z + v.w);
    }
    #pragma unroll
    for (int o = 8; o > 0; o >>= 1) s += __shfl_down_sync(0xffffffffu, s, o, 16);
    if (l == 0) lv[b] = 10.0f * log10f(s * cnorm);
    __syncthreads();

    if (tid < 64) {
        float v = lv[tid];
        #pragma unroll
        for (int o = 16; o > 0; o >>= 1) v += __shfl_down_sync(0xffffffffu, v, o);
        if ((tid & 31) == 0) red[tid >> 5] = v;
    }
    __syncthreads();
    if (tid == 0) out[0] = (red[0] + red[1]) * (1.0f / (float)BATCH);
}

extern "C" void kernel_launch(void* const* d_in, const int* in_sizes, int n_in,
                              void* d_out, int out_size)
{
    const float* x = (const float*)d_in[0];
    float* out = (float*)d_out;

    double wp = 0.0;
    for (int i = 0; i < 512; ++i) {
        double w = 0.54 - 0.46 * cos(2.0 * M_PI * (double)i / 512.0);
        float wf = (float)w;
        wp += (double)wf * (double)wf;
    }
    float cnorm = (float)(1.0 / (wp * 3152.0 * (double)NSEG));

    dim3 grid(NPAIR / 2, BATCH);
    fft_pair_kernel<<<grid, 128>>>(x);
    reduce_all_kernel<<<1, 1024>>>(cnorm, out);
}